// round 15
// baseline (speedup 1.0000x reference)
#include <cuda_runtime.h>
#include <cuda_fp16.h>
#include <cstdint>

#define B_SZ 16384
#define FDIM 2048
#define HID  256
#define NN   9
#define BROWS (B_SZ * NN)   /* 147456 */

// ---------------- scratch (static device globals; no allocations) ----------
__device__ __align__(256) __half g_X[(size_t)B_SZ * FDIM];                 // conc fp16
__device__ __align__(256) __half g_ns[(size_t)BROWS * HID];                // node states fp16
__device__ __align__(256) __half g_W1[(size_t)(NN * HID) * FDIM];          // f2n_w fp16
__device__ __align__(256) __half g_W2[512 * 256];                          // Wc fp16
__device__ __align__(256) __half g_Y[(size_t)BROWS * 512];                 // step GEMM out (fp16)
__device__ __align__(256) float g_Wc[512 * 256];                           // [U1 ; U2*msg_w]
__device__ float g_c[256];                                                 // U2*msg_b + upd_b

// ---------------- PTX helpers (baseline sm_80/sm_100 features only) --------
static __device__ __forceinline__ uint32_t smem_u32(const void* p) {
    uint32_t a;
    asm("{ .reg .u64 t; cvta.to.shared.u64 t, %1; cvt.u32.u64 %0, t; }" : "=r"(a) : "l"(p));
    return a;
}
static __device__ __forceinline__ void cp16(uint32_t s, const void* g) {
    asm volatile("cp.async.cg.shared.global [%0], [%1], 16;" :: "r"(s), "l"(g));
}
static __device__ __forceinline__ void cp_commit() { asm volatile("cp.async.commit_group;"); }
template<int N> static __device__ __forceinline__ void cp_wait() {
    asm volatile("cp.async.wait_group %0;" :: "n"(N));
}
#define LDMX4(r0, r1, r2, r3, a) \
    asm volatile("ldmatrix.sync.aligned.m8n8.x4.shared.b16 {%0,%1,%2,%3}, [%4];" \
        : "=r"(r0), "=r"(r1), "=r"(r2), "=r"(r3) : "r"(a))
#define MMA(c, a, b) \
    asm volatile("mma.sync.aligned.m16n8k16.row.col.f32.f16.f16.f32 " \
        "{%0,%1,%2,%3},{%4,%5,%6,%7},{%8,%9},{%0,%1,%2,%3};" \
        : "+f"((c)[0]), "+f"((c)[1]), "+f"((c)[2]), "+f"((c)[3]) \
        : "r"((a)[0]), "r"((a)[1]), "r"((a)[2]), "r"((a)[3]), "r"((b)[0]), "r"((b)[1]))

static __device__ __forceinline__ uint32_t pack_h2(__half a, __half b) {
    return (uint32_t)__half_as_ushort(a) | ((uint32_t)__half_as_ushort(b) << 16);
}

// ---------------- setup: Wc = [U1 ; U2*msg_w], c = U2*msg_b + upd_b --------
__global__ void setup_kernel(const float* __restrict__ upd_w,
                             const float* __restrict__ msg_w,
                             const float* __restrict__ upd_b,
                             const float* __restrict__ msg_b) {
    int o = blockIdx.x;
    int k = threadIdx.x;  // 256
    if (o < 256) {
        g_Wc[o * 256 + k] = upd_w[o * 512 + k];
    } else if (o < 512) {
        int oo = o - 256;
        float s = 0.f;
        #pragma unroll 8
        for (int t = 0; t < 256; ++t)
            s = fmaf(upd_w[oo * 512 + 256 + t], msg_w[t * 256 + k], s);
        g_Wc[o * 256 + k] = s;
    } else {
        float s = upd_b[k];
        for (int t = 0; t < 256; ++t)
            s = fmaf(upd_w[k * 512 + 256 + t], msg_b[t], s);
        g_c[k] = s;
    }
}

// ---------------- fp32 -> fp16 ---------------------------------------------
__global__ void tohalf_kernel(const float* __restrict__ x, __half* __restrict__ o, int n4) {
    int i = blockIdx.x * blockDim.x + threadIdx.x;
    if (i >= n4) return;
    float4 v = ((const float4*)x)[i];
    uint2 p;
    p.x = pack_h2(__float2half(v.x), __float2half(v.y));
    p.y = pack_h2(__float2half(v.z), __float2half(v.w));
    ((uint2*)o)[i] = p;
}

// ---------------- fp16 NT GEMM on mma.sync ---------------------------------
// C[M,N] = A[M,K] * B[N,K]^T   (fp16 in, fp32 acc)
// CTA tile 128x128, BK=32, 8 warps of 64x32, ldmatrix + 2-stage cp.async.
// EPI=0: fp16 store to Yout(ldc). EPI=1: fused biases -> fp16 ns.
#define PITCH   80                    /* bytes per 32-half row (16B pad) */
#define TILE_SM (128 * PITCH)         /* 10240 B */
#define STAGE_SM (2 * TILE_SM)        /* 20480 B: A, B */
#define SMEM_DYN (2 * STAGE_SM)       /* 40960 B */

template<int EPI>
__global__ __launch_bounds__(256, 2)
void gemm_mma(const __half* __restrict__ A, const __half* __restrict__ B,
              int K, __half* __restrict__ Yout, int ldc,
              __half* __restrict__ ns,
              const float* __restrict__ colBias, const float* __restrict__ hBias,
              const float* __restrict__ hScale, const float* __restrict__ logits) {
    extern __shared__ char smem_raw[];
    const uint32_t sbase = smem_u32(smem_raw);
    const int tid = threadIdx.x;
    const int wid = tid >> 5, lane = tid & 31;
    const int m0 = blockIdx.y * 128;
    const int n0 = blockIdx.x * 128;
    const int m_w = (wid & 1) * 64;        // warp row offset in tile
    const int n_w = (wid >> 1) * 32;       // warp col offset in tile (0,32,64,96)

    const __half* gA = A + (size_t)m0 * K;
    const __half* gB = B + (size_t)n0 * K;

    // ldmatrix lane-address components
    const int aRow  = m_w + (lane & 15);                       // + mb*16
    const int aColB = (lane >> 4) << 4;                        // 0 / 16 bytes
    const int bRow  = n_w + ((lane >> 4) << 3) + (lane & 7);   // + g*16
    const int bColB = ((lane >> 3) & 1) << 4;

    float acc[4][4][4];                                        // [mb][n8b][frag]
    #pragma unroll
    for (int a = 0; a < 4; ++a)
        #pragma unroll
        for (int b = 0; b < 4; ++b)
            #pragma unroll
            for (int c = 0; c < 4; ++c) acc[a][b][c] = 0.f;

    const int nchunk = K >> 5;

    auto load_chunk = [&](int kt, int s) {
        uint32_t st = sbase + (uint32_t)s * STAGE_SM;
        int k0 = kt * 32;
        #pragma unroll
        for (int i = 0; i < 2; ++i) {
            int id = tid + i * 256;
            int r = id >> 2, ch = id & 3;
            cp16(st + (uint32_t)(r * PITCH + ch * 16), gA + (size_t)r * K + k0 + ch * 8);
            cp16(st + TILE_SM + (uint32_t)(r * PITCH + ch * 16), gB + (size_t)r * K + k0 + ch * 8);
        }
        cp_commit();
    };

    load_chunk(0, 0);
    load_chunk(1, 1);

    for (int kt = 0; kt < nchunk; ++kt) {
        const int s = kt & 1;
        if (kt + 1 < nchunk) cp_wait<1>(); else cp_wait<0>();
        __syncthreads();

        const uint32_t tA = sbase + (uint32_t)s * STAGE_SM;
        const uint32_t tB = tA + TILE_SM;

        #pragma unroll
        for (int kb = 0; kb < 2; ++kb) {
            const uint32_t aoff = (uint32_t)(kb * 32 + aColB);
            const uint32_t boff = (uint32_t)(kb * 32 + bColB);
            uint32_t af[4][4], bf[2][4];

            #pragma unroll
            for (int mb = 0; mb < 4; ++mb)
                LDMX4(af[mb][0], af[mb][1], af[mb][2], af[mb][3],
                      tA + (uint32_t)((aRow + mb * 16) * PITCH) + aoff);
            #pragma unroll
            for (int gg = 0; gg < 2; ++gg)
                LDMX4(bf[gg][0], bf[gg][1], bf[gg][2], bf[gg][3],
                      tB + (uint32_t)((bRow + gg * 16) * PITCH) + boff);
            #pragma unroll
            for (int mb = 0; mb < 4; ++mb)
                #pragma unroll
                for (int nb = 0; nb < 4; ++nb)
                    MMA(acc[mb][nb], af[mb], &bf[nb >> 1][(nb & 1) * 2]);
        }

        __syncthreads();
        if (kt + 2 < nchunk) load_chunk(kt + 2, s);
    }

    // ---- epilogue ----
    const int g  = lane >> 2;
    const int t2 = (lane & 3) * 2;
    if (EPI == 0) {
        #pragma unroll
        for (int mb = 0; mb < 4; ++mb) {
            const int r0 = m0 + m_w + mb * 16 + g;
            #pragma unroll
            for (int nb = 0; nb < 4; ++nb) {
                const int col = n0 + n_w + nb * 8 + t2;
                *(uint32_t*)&Yout[(size_t)r0 * ldc + col] =
                    pack_h2(__float2half(acc[mb][nb][0]), __float2half(acc[mb][nb][1]));
                *(uint32_t*)&Yout[(size_t)(r0 + 8) * ldc + col] =
                    pack_h2(__float2half(acc[mb][nb][2]), __float2half(acc[mb][nb][3]));
            }
        }
    } else {
        const int node = n0 >> 8;
        #pragma unroll
        for (int mb = 0; mb < 4; ++mb) {
            const int r0 = m0 + m_w + mb * 16 + g;
            const int r1 = r0 + 8;
            const float lg0 = logits[(size_t)r0 * NN + node];
            const float lg1 = logits[(size_t)r1 * NN + node];
            const size_t base0 = ((size_t)r0 * NN + node) * 256;
            const size_t base1 = ((size_t)r1 * NN + node) * 256;
            #pragma unroll
            for (int nb = 0; nb < 4; ++nb) {
                const int col = n0 + n_w + nb * 8 + t2;
                const int h = col & 255;
                const float cb0 = colBias[col] + hBias[h];
                const float cb1 = colBias[col + 1] + hBias[h + 1];
                const float s0 = hScale[h], s1 = hScale[h + 1];
                float v00 = acc[mb][nb][0] + cb0 + lg0 * s0;
                float v01 = acc[mb][nb][1] + cb1 + lg0 * s1;
                float v10 = acc[mb][nb][2] + cb0 + lg1 * s0;
                float v11 = acc[mb][nb][3] + cb1 + lg1 * s1;
                *(uint32_t*)&ns[base0 + h] = pack_h2(__float2half(v00), __float2half(v01));
                *(uint32_t*)&ns[base1 + h] = pack_h2(__float2half(v10), __float2half(v11));
            }
        }
    }
}

// ---------------- combine: adjacency mix + tanh -> fp16 ns -----------------
// Y[b,i,0:256] = ns@U1^T ; Y[b,i,256:512] = ns@(U2*msg_w)^T (=Z)
// new[b,i,h] = tanh(Y1 + sum_j A[i,j] Z[b,j,h] + c[h])
__global__ void combine_kernel(__half* __restrict__ ns, const __half* __restrict__ Y) {
    const int b = blockIdx.x;
    const int h = threadIdx.x;  // 256
    const __half* Yb = Y + (size_t)b * (NN * 512);
    float z[NN];
    float total = 0.f;
    #pragma unroll
    for (int j = 0; j < NN; ++j) { z[j] = __half2float(Yb[j * 512 + 256 + h]); total += z[j]; }
    const float cb = g_c[h];
    const size_t base = (size_t)b * (NN * HID) + h;

    float pre[NN];
    pre[0] = __half2float(Yb[0 * 512 + h]) + total * (1.f / 9.f) + cb;
    pre[1] = __half2float(Yb[1 * 512 + h]) + (z[0] + z[1]) * 0.5f + cb;
    #pragma unroll
    for (int i = 2; i < 7; ++i)
        pre[i] = __half2float(Yb[i * 512 + h]) + (z[0] + z[i] + z[7] + z[8]) * 0.25f + cb;
    const float s78 = (total - z[1]) * 0.125f;
    pre[7] = __half2float(Yb[7 * 512 + h]) + s78 + cb;
    pre[8] = __half2float(Yb[8 * 512 + h]) + s78 + cb;
    #pragma unroll
    for (int i = 0; i < NN; ++i)
        ns[base + i * 256] = __float2half(tanhf(pre[i]));
}

// ---------------- last step: nodes 7/8 combine + output dot ----------------
__global__ void final_kernel(const __half* __restrict__ Y,
                             const float* __restrict__ out_w,
                             const float* __restrict__ out_b,
                             float* __restrict__ out) {
    const int b = blockIdx.x;
    const int lane = threadIdx.x & 31;
    const int node = 7 + (threadIdx.x >> 5);  // warp0 -> node7 (chronic), warp1 -> node8
    const __half* Yb = Y + (size_t)b * (NN * 512);
    float acc = 0.f;
    #pragma unroll
    for (int hh = 0; hh < 8; ++hh) {
        int h = lane + hh * 32;
        float total = 0.f, z1 = 0.f;
        #pragma unroll
        for (int j = 0; j < NN; ++j) {
            float zj = __half2float(Yb[j * 512 + 256 + h]);
            total += zj;
            if (j == 1) z1 = zj;
        }
        float pre = __half2float(Yb[node * 512 + h]) + (total - z1) * 0.125f + g_c[h];
        acc += tanhf(pre) * out_w[h];
    }
    #pragma unroll
    for (int o = 16; o > 0; o >>= 1) acc += __shfl_down_sync(0xffffffffu, acc, o);
    if (lane == 0) out[(node - 7) * B_SZ + b] = acc + out_b[0];
}

// ---------------- launch ---------------------------------------------------
extern "C" void kernel_launch(void* const* d_in, const int* in_sizes, int n_in,
                              void* d_out, int out_size) {
    const float* conc   = (const float*)d_in[0];   // [B, 2048]
    const float* logits = (const float*)d_in[1];   // [B, 9]
    const float* enc_w  = (const float*)d_in[2];   // [256, 1]
    const float* enc_b  = (const float*)d_in[3];   // [256]
    const float* f2n_w  = (const float*)d_in[4];   // [2304, 2048]
    const float* f2n_b  = (const float*)d_in[5];   // [2304]
    const float* msg_w  = (const float*)d_in[6];   // [256, 256]
    const float* msg_b  = (const float*)d_in[7];   // [256]
    const float* upd_w  = (const float*)d_in[8];   // [256, 512]
    const float* upd_b  = (const float*)d_in[9];   // [256]
    const float* out_w  = (const float*)d_in[10];  // [1, 256]
    const float* out_b  = (const float*)d_in[11];  // [1]
    float* out = (float*)d_out;

    __half *X, *ns, *W1, *W2, *Y;
    float *Wc;
    cudaGetSymbolAddress((void**)&X,  g_X);
    cudaGetSymbolAddress((void**)&ns, g_ns);
    cudaGetSymbolAddress((void**)&W1, g_W1);
    cudaGetSymbolAddress((void**)&W2, g_W2);
    cudaGetSymbolAddress((void**)&Y,  g_Y);
    cudaGetSymbolAddress((void**)&Wc, g_Wc);

    cudaFuncSetAttribute((const void*)gemm_mma<0>, cudaFuncAttributeMaxDynamicSharedMemorySize, SMEM_DYN);
    cudaFuncSetAttribute((const void*)gemm_mma<1>, cudaFuncAttributeMaxDynamicSharedMemorySize, SMEM_DYN);

    // fold weights; convert everything to fp16
    setup_kernel<<<513, 256>>>(upd_w, msg_w, upd_b, msg_b);
    int n4 = (B_SZ * FDIM) / 4;
    tohalf_kernel<<<(n4 + 255) / 256, 256>>>(conc, X, n4);
    n4 = (NN * HID * FDIM) / 4;
    tohalf_kernel<<<(n4 + 255) / 256, 256>>>(f2n_w, W1, n4);
    n4 = (512 * 256) / 4;
    tohalf_kernel<<<(n4 + 255) / 256, 256>>>(Wc, W2, n4);

    // ns = conc @ f2n_w^T + biases  -> fp16 node states [B*9, 256]
    gemm_mma<1><<<dim3((NN * HID) / 128, B_SZ / 128), 256, SMEM_DYN>>>(
        X, W1, FDIM, nullptr, 0,
        ns, f2n_b, enc_b, enc_w, logits);

    for (int s = 0; s < 4; ++s) {
        // Y = ns @ Wc^T : [B*9, 256] x [512, 256]^T -> [B*9, 512] fp16
        gemm_mma<0><<<dim3(512 / 128, BROWS / 128), 256, SMEM_DYN>>>(
            ns, W2, HID, Y, 512,
            nullptr, nullptr, nullptr, nullptr, nullptr);
        if (s < 3)
            combine_kernel<<<B_SZ, 256>>>(ns, Y);
        else
            final_kernel<<<B_SZ, 64>>>(Y, out_w, out_b, out);
    }
}

// round 16
// speedup vs baseline: 1.1303x; 1.1303x over previous
#include <cuda_runtime.h>
#include <cuda_fp16.h>
#include <cstdint>

#define B_SZ 16384
#define FDIM 2048
#define HID  256
#define NN   9
#define BROWS (B_SZ * NN)   /* 147456 */

// ---------------- scratch (static device globals; no allocations) ----------
__device__ __align__(256) __half g_X[(size_t)B_SZ * FDIM];                 // conc fp16
__device__ __align__(256) __half g_ns[(size_t)BROWS * HID];                // node states fp16
__device__ __align__(256) __half g_W1[(size_t)(NN * HID) * FDIM];          // f2n_w fp16
__device__ __align__(256) __half g_W2[512 * 256];                          // Wc fp16
__device__ __align__(256) __half g_Y[(size_t)BROWS * 512];                 // step GEMM out (fp16)
__device__ __align__(256) float g_Wc[512 * 256];                           // [U1 ; U2*msg_w]
__device__ float g_c[256];                                                 // U2*msg_b + upd_b

// ---------------- PTX helpers (baseline sm_80/sm_100 features only) --------
static __device__ __forceinline__ uint32_t smem_u32(const void* p) {
    uint32_t a;
    asm("{ .reg .u64 t; cvta.to.shared.u64 t, %1; cvt.u32.u64 %0, t; }" : "=r"(a) : "l"(p));
    return a;
}
static __device__ __forceinline__ void cp16(uint32_t s, const void* g) {
    asm volatile("cp.async.cg.shared.global [%0], [%1], 16;" :: "r"(s), "l"(g));
}
static __device__ __forceinline__ void cp_commit() { asm volatile("cp.async.commit_group;"); }
template<int N> static __device__ __forceinline__ void cp_wait() {
    asm volatile("cp.async.wait_group %0;" :: "n"(N));
}
#define LDMX4(r0, r1, r2, r3, a) \
    asm volatile("ldmatrix.sync.aligned.m8n8.x4.shared.b16 {%0,%1,%2,%3}, [%4];" \
        : "=r"(r0), "=r"(r1), "=r"(r2), "=r"(r3) : "r"(a))
#define MMA(c, a, b) \
    asm volatile("mma.sync.aligned.m16n8k16.row.col.f32.f16.f16.f32 " \
        "{%0,%1,%2,%3},{%4,%5,%6,%7},{%8,%9},{%0,%1,%2,%3};" \
        : "+f"((c)[0]), "+f"((c)[1]), "+f"((c)[2]), "+f"((c)[3]) \
        : "r"((a)[0]), "r"((a)[1]), "r"((a)[2]), "r"((a)[3]), "r"((b)[0]), "r"((b)[1]))

static __device__ __forceinline__ uint32_t pack_h2(__half a, __half b) {
    return (uint32_t)__half_as_ushort(a) | ((uint32_t)__half_as_ushort(b) << 16);
}

// ---------------- setup: Wc = [U1 ; U2*msg_w], c = U2*msg_b + upd_b --------
__global__ void setup_kernel(const float* __restrict__ upd_w,
                             const float* __restrict__ msg_w,
                             const float* __restrict__ upd_b,
                             const float* __restrict__ msg_b) {
    int o = blockIdx.x;
    int k = threadIdx.x;  // 256
    if (o < 256) {
        g_Wc[o * 256 + k] = upd_w[o * 512 + k];
    } else if (o < 512) {
        int oo = o - 256;
        float s = 0.f;
        #pragma unroll 8
        for (int t = 0; t < 256; ++t)
            s = fmaf(upd_w[oo * 512 + 256 + t], msg_w[t * 256 + k], s);
        g_Wc[o * 256 + k] = s;
    } else {
        float s = upd_b[k];
        for (int t = 0; t < 256; ++t)
            s = fmaf(upd_w[k * 512 + 256 + t], msg_b[t], s);
        g_c[k] = s;
    }
}

// ---------------- fp32 -> fp16 ---------------------------------------------
__global__ void tohalf_kernel(const float* __restrict__ x, __half* __restrict__ o, int n4) {
    int i = blockIdx.x * blockDim.x + threadIdx.x;
    if (i >= n4) return;
    float4 v = ((const float4*)x)[i];
    uint2 p;
    p.x = pack_h2(__float2half(v.x), __float2half(v.y));
    p.y = pack_h2(__float2half(v.z), __float2half(v.w));
    ((uint2*)o)[i] = p;
}

// ---------------- fp16 NT GEMM on mma.sync ---------------------------------
// C[M,N] = A[M,K] * B[N,K]^T   (fp16 in, fp32 acc)
// CTA tile 128x128, BK=32, 4 warps of 64x64.
// 3-stage cp.async, ONE __syncthreads per k-chunk, loads issued before compute
// (CUTLASS sm80 pattern): at iter kt, the sync proves all warps finished
// compute(kt-1), so stage (kt+2)%3 == (kt-1)%3 is safe to overwrite.
// EPI=0: fp16 store to Yout(ldc). EPI=1: fused biases -> fp16 ns.
#define PITCH   80                    /* bytes per 32-half row (16B pad) */
#define TILE_SM (128 * PITCH)         /* 10240 B */
#define STAGE_SM (2 * TILE_SM)        /* 20480 B: A, B */
#define SMEM_DYN (3 * STAGE_SM)       /* 61440 B */

template<int EPI>
__global__ __launch_bounds__(128, 2)
void gemm_mma(const __half* __restrict__ A, const __half* __restrict__ B,
              int K, __half* __restrict__ Yout, int ldc,
              __half* __restrict__ ns,
              const float* __restrict__ colBias, const float* __restrict__ hBias,
              const float* __restrict__ hScale, const float* __restrict__ logits) {
    extern __shared__ char smem_raw[];
    const uint32_t sbase = smem_u32(smem_raw);
    const int tid = threadIdx.x;
    const int wid = tid >> 5, lane = tid & 31;
    const int m0 = blockIdx.y * 128;
    const int n0 = blockIdx.x * 128;
    const int m_w = (wid & 1) * 64;        // warp row offset in tile
    const int n_w = (wid >> 1) * 64;       // warp col offset in tile

    const __half* gA = A + (size_t)m0 * K;
    const __half* gB = B + (size_t)n0 * K;

    // ldmatrix lane-address components
    const int aRow  = m_w + (lane & 15);                       // + mb*16
    const int aColB = (lane >> 4) << 4;                        // 0 / 16 bytes
    const int bRow  = n_w + ((lane >> 4) << 3) + (lane & 7);   // + g*16
    const int bColB = ((lane >> 3) & 1) << 4;

    float acc[4][8][4];                                        // [mb][n8b][frag]
    #pragma unroll
    for (int a = 0; a < 4; ++a)
        #pragma unroll
        for (int b = 0; b < 8; ++b)
            #pragma unroll
            for (int c = 0; c < 4; ++c) acc[a][b][c] = 0.f;

    const int nchunk = K >> 5;

    auto load_chunk = [&](int kt, int s) {
        uint32_t st = sbase + (uint32_t)s * STAGE_SM;
        int k0 = kt * 32;
        #pragma unroll
        for (int i = 0; i < 4; ++i) {
            int id = tid + i * 128;
            int r = id >> 2, ch = id & 3;
            cp16(st + (uint32_t)(r * PITCH + ch * 16), gA + (size_t)r * K + k0 + ch * 8);
            cp16(st + TILE_SM + (uint32_t)(r * PITCH + ch * 16), gB + (size_t)r * K + k0 + ch * 8);
        }
        cp_commit();
    };

    load_chunk(0, 0);
    load_chunk(1, 1);

    for (int kt = 0; kt < nchunk; ++kt) {
        const int s = kt % 3;
        if (kt + 1 < nchunk) cp_wait<1>(); else cp_wait<0>();
        __syncthreads();

        // issue next loads BEFORE compute (overlaps with this chunk's MMAs);
        // target stage (kt+2)%3 == (kt-1)%3, proven free by the sync above.
        if (kt + 2 < nchunk) load_chunk(kt + 2, (kt + 2) % 3);

        const uint32_t tA = sbase + (uint32_t)s * STAGE_SM;
        const uint32_t tB = tA + TILE_SM;

        #pragma unroll
        for (int kb = 0; kb < 2; ++kb) {
            const uint32_t aoff = (uint32_t)(kb * 32 + aColB);
            const uint32_t boff = (uint32_t)(kb * 32 + bColB);
            uint32_t af[4][4], bf[4][4];

            #pragma unroll
            for (int mb = 0; mb < 4; ++mb)
                LDMX4(af[mb][0], af[mb][1], af[mb][2], af[mb][3],
                      tA + (uint32_t)((aRow + mb * 16) * PITCH) + aoff);
            #pragma unroll
            for (int gg = 0; gg < 4; ++gg)
                LDMX4(bf[gg][0], bf[gg][1], bf[gg][2], bf[gg][3],
                      tB + (uint32_t)((bRow + gg * 16) * PITCH) + boff);
            #pragma unroll
            for (int mb = 0; mb < 4; ++mb)
                #pragma unroll
                for (int nb = 0; nb < 8; ++nb)
                    MMA(acc[mb][nb], af[mb], &bf[nb >> 1][(nb & 1) * 2]);
        }
    }

    // ---- epilogue ----
    const int g  = lane >> 2;
    const int t2 = (lane & 3) * 2;
    if (EPI == 0) {
        #pragma unroll
        for (int mb = 0; mb < 4; ++mb) {
            const int r0 = m0 + m_w + mb * 16 + g;
            #pragma unroll
            for (int nb = 0; nb < 8; ++nb) {
                const int col = n0 + n_w + nb * 8 + t2;
                *(uint32_t*)&Yout[(size_t)r0 * ldc + col] =
                    pack_h2(__float2half(acc[mb][nb][0]), __float2half(acc[mb][nb][1]));
                *(uint32_t*)&Yout[(size_t)(r0 + 8) * ldc + col] =
                    pack_h2(__float2half(acc[mb][nb][2]), __float2half(acc[mb][nb][3]));
            }
        }
    } else {
        const int node = n0 >> 8;
        #pragma unroll
        for (int mb = 0; mb < 4; ++mb) {
            const int r0 = m0 + m_w + mb * 16 + g;
            const int r1 = r0 + 8;
            const float lg0 = logits[(size_t)r0 * NN + node];
            const float lg1 = logits[(size_t)r1 * NN + node];
            const size_t base0 = ((size_t)r0 * NN + node) * 256;
            const size_t base1 = ((size_t)r1 * NN + node) * 256;
            #pragma unroll
            for (int nb = 0; nb < 8; ++nb) {
                const int col = n0 + n_w + nb * 8 + t2;
                const int h = col & 255;
                const float cb0 = colBias[col] + hBias[h];
                const float cb1 = colBias[col + 1] + hBias[h + 1];
                const float s0 = hScale[h], s1 = hScale[h + 1];
                float v00 = acc[mb][nb][0] + cb0 + lg0 * s0;
                float v01 = acc[mb][nb][1] + cb1 + lg0 * s1;
                float v10 = acc[mb][nb][2] + cb0 + lg1 * s0;
                float v11 = acc[mb][nb][3] + cb1 + lg1 * s1;
                *(uint32_t*)&ns[base0 + h] = pack_h2(__float2half(v00), __float2half(v01));
                *(uint32_t*)&ns[base1 + h] = pack_h2(__float2half(v10), __float2half(v11));
            }
        }
    }
}

// ---------------- combine: adjacency mix + tanh -> fp16 ns -----------------
// Y[b,i,0:256] = ns@U1^T ; Y[b,i,256:512] = ns@(U2*msg_w)^T (=Z)
// new[b,i,h] = tanh(Y1 + sum_j A[i,j] Z[b,j,h] + c[h])
__global__ void combine_kernel(__half* __restrict__ ns, const __half* __restrict__ Y) {
    const int b = blockIdx.x;
    const int h = threadIdx.x;  // 256
    const __half* Yb = Y + (size_t)b * (NN * 512);
    float z[NN];
    float total = 0.f;
    #pragma unroll
    for (int j = 0; j < NN; ++j) { z[j] = __half2float(Yb[j * 512 + 256 + h]); total += z[j]; }
    const float cb = g_c[h];
    const size_t base = (size_t)b * (NN * HID) + h;

    float pre[NN];
    pre[0] = __half2float(Yb[0 * 512 + h]) + total * (1.f / 9.f) + cb;
    pre[1] = __half2float(Yb[1 * 512 + h]) + (z[0] + z[1]) * 0.5f + cb;
    #pragma unroll
    for (int i = 2; i < 7; ++i)
        pre[i] = __half2float(Yb[i * 512 + h]) + (z[0] + z[i] + z[7] + z[8]) * 0.25f + cb;
    const float s78 = (total - z[1]) * 0.125f;
    pre[7] = __half2float(Yb[7 * 512 + h]) + s78 + cb;
    pre[8] = __half2float(Yb[8 * 512 + h]) + s78 + cb;
    #pragma unroll
    for (int i = 0; i < NN; ++i)
        ns[base + i * 256] = __float2half(tanhf(pre[i]));
}

// ---------------- last step: nodes 7/8 combine + output dot ----------------
__global__ void final_kernel(const __half* __restrict__ Y,
                             const float* __restrict__ out_w,
                             const float* __restrict__ out_b,
                             float* __restrict__ out) {
    const int b = blockIdx.x;
    const int lane = threadIdx.x & 31;
    const int node = 7 + (threadIdx.x >> 5);  // warp0 -> node7 (chronic), warp1 -> node8
    const __half* Yb = Y + (size_t)b * (NN * 512);
    float acc = 0.f;
    #pragma unroll
    for (int hh = 0; hh < 8; ++hh) {
        int h = lane + hh * 32;
        float total = 0.f, z1 = 0.f;
        #pragma unroll
        for (int j = 0; j < NN; ++j) {
            float zj = __half2float(Yb[j * 512 + 256 + h]);
            total += zj;
            if (j == 1) z1 = zj;
        }
        float pre = __half2float(Yb[node * 512 + h]) + (total - z1) * 0.125f + g_c[h];
        acc += tanhf(pre) * out_w[h];
    }
    #pragma unroll
    for (int o = 16; o > 0; o >>= 1) acc += __shfl_down_sync(0xffffffffu, acc, o);
    if (lane == 0) out[(node - 7) * B_SZ + b] = acc + out_b[0];
}

// ---------------- launch ---------------------------------------------------
extern "C" void kernel_launch(void* const* d_in, const int* in_sizes, int n_in,
                              void* d_out, int out_size) {
    const float* conc   = (const float*)d_in[0];   // [B, 2048]
    const float* logits = (const float*)d_in[1];   // [B, 9]
    const float* enc_w  = (const float*)d_in[2];   // [256, 1]
    const float* enc_b  = (const float*)d_in[3];   // [256]
    const float* f2n_w  = (const float*)d_in[4];   // [2304, 2048]
    const float* f2n_b  = (const float*)d_in[5];   // [2304]
    const float* msg_w  = (const float*)d_in[6];   // [256, 256]
    const float* msg_b  = (const float*)d_in[7];   // [256]
    const float* upd_w  = (const float*)d_in[8];   // [256, 512]
    const float* upd_b  = (const float*)d_in[9];   // [256]
    const float* out_w  = (const float*)d_in[10];  // [1, 256]
    const float* out_b  = (const float*)d_in[11];  // [1]
    float* out = (float*)d_out;

    __half *X, *ns, *W1, *W2, *Y;
    float *Wc;
    cudaGetSymbolAddress((void**)&X,  g_X);
    cudaGetSymbolAddress((void**)&ns, g_ns);
    cudaGetSymbolAddress((void**)&W1, g_W1);
    cudaGetSymbolAddress((void**)&W2, g_W2);
    cudaGetSymbolAddress((void**)&Y,  g_Y);
    cudaGetSymbolAddress((void**)&Wc, g_Wc);

    cudaFuncSetAttribute((const void*)gemm_mma<0>, cudaFuncAttributeMaxDynamicSharedMemorySize, SMEM_DYN);
    cudaFuncSetAttribute((const void*)gemm_mma<1>, cudaFuncAttributeMaxDynamicSharedMemorySize, SMEM_DYN);

    // fold weights; convert everything to fp16
    setup_kernel<<<513, 256>>>(upd_w, msg_w, upd_b, msg_b);
    int n4 = (B_SZ * FDIM) / 4;
    tohalf_kernel<<<(n4 + 255) / 256, 256>>>(conc, X, n4);
    n4 = (NN * HID * FDIM) / 4;
    tohalf_kernel<<<(n4 + 255) / 256, 256>>>(f2n_w, W1, n4);
    n4 = (512 * 256) / 4;
    tohalf_kernel<<<(n4 + 255) / 256, 256>>>(Wc, W2, n4);

    // ns = conc @ f2n_w^T + biases  -> fp16 node states [B*9, 256]
    gemm_mma<1><<<dim3((NN * HID) / 128, B_SZ / 128), 128, SMEM_DYN>>>(
        X, W1, FDIM, nullptr, 0,
        ns, f2n_b, enc_b, enc_w, logits);

    for (int s = 0; s < 4; ++s) {
        // Y = ns @ Wc^T : [B*9, 256] x [512, 256]^T -> [B*9, 512] fp16
        gemm_mma<0><<<dim3(512 / 128, BROWS / 128), 128, SMEM_DYN>>>(
            ns, W2, HID, Y, 512,
            nullptr, nullptr, nullptr, nullptr, nullptr);
        if (s < 3)
            combine_kernel<<<B_SZ, 256>>>(ns, Y);
        else
            final_kernel<<<B_SZ, 64>>>(Y, out_w, out_b, out);
    }
}

// round 17
// speedup vs baseline: 1.1394x; 1.0080x over previous
#include <cuda_runtime.h>
#include <cuda_fp16.h>
#include <cstdint>

#define B_SZ 16384
#define FDIM 2048
#define HID  256
#define NN   9
#define BROWS (B_SZ * NN)   /* 147456 */

// ---------------- scratch (static device globals; no allocations) ----------
__device__ __align__(256) __half g_X[(size_t)B_SZ * FDIM];                 // conc fp16
__device__ __align__(256) __half g_ns[(size_t)BROWS * HID];                // node states fp16
__device__ __align__(256) __half g_W1[(size_t)(NN * HID) * FDIM];          // f2n_w fp16
__device__ __align__(256) __half g_W2[512 * 256];                          // Wc fp16
__device__ __align__(256) __half g_Y[(size_t)BROWS * 512];                 // step GEMM out (fp16)
__device__ __align__(256) float g_Wc[512 * 256];                           // [U1 ; U2*msg_w]
__device__ float g_c[256];                                                 // U2*msg_b + upd_b

// ---------------- PTX helpers (baseline sm_80/sm_100 features only) --------
static __device__ __forceinline__ uint32_t smem_u32(const void* p) {
    uint32_t a;
    asm("{ .reg .u64 t; cvta.to.shared.u64 t, %1; cvt.u32.u64 %0, t; }" : "=r"(a) : "l"(p));
    return a;
}
static __device__ __forceinline__ void cp16(uint32_t s, const void* g) {
    asm volatile("cp.async.cg.shared.global [%0], [%1], 16;" :: "r"(s), "l"(g));
}
static __device__ __forceinline__ void cp_commit() { asm volatile("cp.async.commit_group;"); }
template<int N> static __device__ __forceinline__ void cp_wait() {
    asm volatile("cp.async.wait_group %0;" :: "n"(N));
}
#define LDMX4(r0, r1, r2, r3, a) \
    asm volatile("ldmatrix.sync.aligned.m8n8.x4.shared.b16 {%0,%1,%2,%3}, [%4];" \
        : "=r"(r0), "=r"(r1), "=r"(r2), "=r"(r3) : "r"(a))
#define MMA(c, a, b) \
    asm volatile("mma.sync.aligned.m16n8k16.row.col.f32.f16.f16.f32 " \
        "{%0,%1,%2,%3},{%4,%5,%6,%7},{%8,%9},{%0,%1,%2,%3};" \
        : "+f"((c)[0]), "+f"((c)[1]), "+f"((c)[2]), "+f"((c)[3]) \
        : "r"((a)[0]), "r"((a)[1]), "r"((a)[2]), "r"((a)[3]), "r"((b)[0]), "r"((b)[1]))

static __device__ __forceinline__ uint32_t pack_h2(__half a, __half b) {
    return (uint32_t)__half_as_ushort(a) | ((uint32_t)__half_as_ushort(b) << 16);
}

// ---------------- setup: Wc = [U1 ; U2*msg_w], c = U2*msg_b + upd_b --------
__global__ void setup_kernel(const float* __restrict__ upd_w,
                             const float* __restrict__ msg_w,
                             const float* __restrict__ upd_b,
                             const float* __restrict__ msg_b) {
    int o = blockIdx.x;
    int k = threadIdx.x;  // 256
    if (o < 256) {
        g_Wc[o * 256 + k] = upd_w[o * 512 + k];
    } else if (o < 512) {
        int oo = o - 256;
        float s = 0.f;
        #pragma unroll 8
        for (int t = 0; t < 256; ++t)
            s = fmaf(upd_w[oo * 512 + 256 + t], msg_w[t * 256 + k], s);
        g_Wc[o * 256 + k] = s;
    } else {
        float s = upd_b[k];
        for (int t = 0; t < 256; ++t)
            s = fmaf(upd_w[k * 512 + 256 + t], msg_b[t], s);
        g_c[k] = s;
    }
}

// ---------------- fp32 -> fp16 ---------------------------------------------
__global__ void tohalf_kernel(const float* __restrict__ x, __half* __restrict__ o, int n4) {
    int i = blockIdx.x * blockDim.x + threadIdx.x;
    if (i >= n4) return;
    float4 v = ((const float4*)x)[i];
    uint2 p;
    p.x = pack_h2(__float2half(v.x), __float2half(v.y));
    p.y = pack_h2(__float2half(v.z), __float2half(v.w));
    ((uint2*)o)[i] = p;
}

// ---------------- fp16 NT GEMM on mma.sync ---------------------------------
// C[M,N] = A[M,K] * B[N,K]^T   (fp16 in, fp32 acc)
// CTA tile 128x128, BK=64, 4 warps of 64x64.
// 3-stage cp.async, ONE __syncthreads per k-chunk, loads issued before compute
// (CUTLASS sm80 pattern): at iter kt, the sync proves all warps finished
// compute(kt-1), so stage (kt+2)%3 == (kt-1)%3 is safe to overwrite.
// EPI=0: fp16 store to Yout(ldc). EPI=1: fused biases -> fp16 ns.
#define PITCH   144                   /* bytes per 64-half row (16B pad) */
#define TILE_SM (128 * PITCH)         /* 18432 B */
#define STAGE_SM (2 * TILE_SM)        /* 36864 B: A, B */
#define SMEM_DYN (3 * STAGE_SM)       /* 110592 B; 2 CTA/SM = 221184 < 228KB */

template<int EPI>
__global__ __launch_bounds__(128, 2)
void gemm_mma(const __half* __restrict__ A, const __half* __restrict__ B,
              int K, __half* __restrict__ Yout, int ldc,
              __half* __restrict__ ns,
              const float* __restrict__ colBias, const float* __restrict__ hBias,
              const float* __restrict__ hScale, const float* __restrict__ logits) {
    extern __shared__ char smem_raw[];
    const uint32_t sbase = smem_u32(smem_raw);
    const int tid = threadIdx.x;
    const int wid = tid >> 5, lane = tid & 31;
    const int m0 = blockIdx.y * 128;
    const int n0 = blockIdx.x * 128;
    const int m_w = (wid & 1) * 64;        // warp row offset in tile
    const int n_w = (wid >> 1) * 64;       // warp col offset in tile

    const __half* gA = A + (size_t)m0 * K;
    const __half* gB = B + (size_t)n0 * K;

    // ldmatrix lane-address components
    const int aRow  = m_w + (lane & 15);                       // + mb*16
    const int aColB = (lane >> 4) << 4;                        // 0 / 16 bytes
    const int bRow  = n_w + ((lane >> 4) << 3) + (lane & 7);   // + g*16
    const int bColB = ((lane >> 3) & 1) << 4;

    float acc[4][8][4];                                        // [mb][n8b][frag]
    #pragma unroll
    for (int a = 0; a < 4; ++a)
        #pragma unroll
        for (int b = 0; b < 8; ++b)
            #pragma unroll
            for (int c = 0; c < 4; ++c) acc[a][b][c] = 0.f;

    const int nchunk = K >> 6;

    auto load_chunk = [&](int kt, int s) {
        uint32_t st = sbase + (uint32_t)s * STAGE_SM;
        int k0 = kt * 64;
        #pragma unroll
        for (int i = 0; i < 8; ++i) {
            int id = tid + i * 128;
            int r = id >> 3, ch = id & 7;
            cp16(st + (uint32_t)(r * PITCH + ch * 16), gA + (size_t)r * K + k0 + ch * 8);
            cp16(st + TILE_SM + (uint32_t)(r * PITCH + ch * 16), gB + (size_t)r * K + k0 + ch * 8);
        }
        cp_commit();
    };

    load_chunk(0, 0);
    load_chunk(1, 1);

    for (int kt = 0; kt < nchunk; ++kt) {
        const int s = kt % 3;
        if (kt + 1 < nchunk) cp_wait<1>(); else cp_wait<0>();
        __syncthreads();

        // issue next loads BEFORE compute (overlaps with this chunk's MMAs);
        // target stage (kt+2)%3 == (kt-1)%3, proven free by the sync above.
        if (kt + 2 < nchunk) load_chunk(kt + 2, (kt + 2) % 3);

        const uint32_t tA = sbase + (uint32_t)s * STAGE_SM;
        const uint32_t tB = tA + TILE_SM;

        #pragma unroll
        for (int kb = 0; kb < 4; ++kb) {
            const uint32_t aoff = (uint32_t)(kb * 32 + aColB);
            const uint32_t boff = (uint32_t)(kb * 32 + bColB);
            uint32_t af[4][4], bf[4][4];

            #pragma unroll
            for (int mb = 0; mb < 4; ++mb)
                LDMX4(af[mb][0], af[mb][1], af[mb][2], af[mb][3],
                      tA + (uint32_t)((aRow + mb * 16) * PITCH) + aoff);
            #pragma unroll
            for (int gg = 0; gg < 4; ++gg)
                LDMX4(bf[gg][0], bf[gg][1], bf[gg][2], bf[gg][3],
                      tB + (uint32_t)((bRow + gg * 16) * PITCH) + boff);
            #pragma unroll
            for (int mb = 0; mb < 4; ++mb)
                #pragma unroll
                for (int nb = 0; nb < 8; ++nb)
                    MMA(acc[mb][nb], af[mb], &bf[nb >> 1][(nb & 1) * 2]);
        }
    }

    // ---- epilogue ----
    const int g  = lane >> 2;
    const int t2 = (lane & 3) * 2;
    if (EPI == 0) {
        #pragma unroll
        for (int mb = 0; mb < 4; ++mb) {
            const int r0 = m0 + m_w + mb * 16 + g;
            #pragma unroll
            for (int nb = 0; nb < 8; ++nb) {
                const int col = n0 + n_w + nb * 8 + t2;
                *(uint32_t*)&Yout[(size_t)r0 * ldc + col] =
                    pack_h2(__float2half(acc[mb][nb][0]), __float2half(acc[mb][nb][1]));
                *(uint32_t*)&Yout[(size_t)(r0 + 8) * ldc + col] =
                    pack_h2(__float2half(acc[mb][nb][2]), __float2half(acc[mb][nb][3]));
            }
        }
    } else {
        const int node = n0 >> 8;
        #pragma unroll
        for (int mb = 0; mb < 4; ++mb) {
            const int r0 = m0 + m_w + mb * 16 + g;
            const int r1 = r0 + 8;
            const float lg0 = logits[(size_t)r0 * NN + node];
            const float lg1 = logits[(size_t)r1 * NN + node];
            const size_t base0 = ((size_t)r0 * NN + node) * 256;
            const size_t base1 = ((size_t)r1 * NN + node) * 256;
            #pragma unroll
            for (int nb = 0; nb < 8; ++nb) {
                const int col = n0 + n_w + nb * 8 + t2;
                const int h = col & 255;
                const float cb0 = colBias[col] + hBias[h];
                const float cb1 = colBias[col + 1] + hBias[h + 1];
                const float s0 = hScale[h], s1 = hScale[h + 1];
                float v00 = acc[mb][nb][0] + cb0 + lg0 * s0;
                float v01 = acc[mb][nb][1] + cb1 + lg0 * s1;
                float v10 = acc[mb][nb][2] + cb0 + lg1 * s0;
                float v11 = acc[mb][nb][3] + cb1 + lg1 * s1;
                *(uint32_t*)&ns[base0 + h] = pack_h2(__float2half(v00), __float2half(v01));
                *(uint32_t*)&ns[base1 + h] = pack_h2(__float2half(v10), __float2half(v11));
            }
        }
    }
}

// ---------------- combine: adjacency mix + tanh -> fp16 ns -----------------
// Y[b,i,0:256] = ns@U1^T ; Y[b,i,256:512] = ns@(U2*msg_w)^T (=Z)
// new[b,i,h] = tanh(Y1 + sum_j A[i,j] Z[b,j,h] + c[h])
__global__ void combine_kernel(__half* __restrict__ ns, const __half* __restrict__ Y) {
    const int b = blockIdx.x;
    const int h = threadIdx.x;  // 256
    const __half* Yb = Y + (size_t)b * (NN * 512);
    float z[NN];
    float total = 0.f;
    #pragma unroll
    for (int j = 0; j < NN; ++j) { z[j] = __half2float(Yb[j * 512 + 256 + h]); total += z[j]; }
    const float cb = g_c[h];
    const size_t base = (size_t)b * (NN * HID) + h;

    float pre[NN];
    pre[0] = __half2float(Yb[0 * 512 + h]) + total * (1.f / 9.f) + cb;
    pre[1] = __half2float(Yb[1 * 512 + h]) + (z[0] + z[1]) * 0.5f + cb;
    #pragma unroll
    for (int i = 2; i < 7; ++i)
        pre[i] = __half2float(Yb[i * 512 + h]) + (z[0] + z[i] + z[7] + z[8]) * 0.25f + cb;
    const float s78 = (total - z[1]) * 0.125f;
    pre[7] = __half2float(Yb[7 * 512 + h]) + s78 + cb;
    pre[8] = __half2float(Yb[8 * 512 + h]) + s78 + cb;
    #pragma unroll
    for (int i = 0; i < NN; ++i)
        ns[base + i * 256] = __float2half(tanhf(pre[i]));
}

// ---------------- last step: nodes 7/8 combine + output dot ----------------
__global__ void final_kernel(const __half* __restrict__ Y,
                             const float* __restrict__ out_w,
                             const float* __restrict__ out_b,
                             float* __restrict__ out) {
    const int b = blockIdx.x;
    const int lane = threadIdx.x & 31;
    const int node = 7 + (threadIdx.x >> 5);  // warp0 -> node7 (chronic), warp1 -> node8
    const __half* Yb = Y + (size_t)b * (NN * 512);
    float acc = 0.f;
    #pragma unroll
    for (int hh = 0; hh < 8; ++hh) {
        int h = lane + hh * 32;
        float total = 0.f, z1 = 0.f;
        #pragma unroll
        for (int j = 0; j < NN; ++j) {
            float zj = __half2float(Yb[j * 512 + 256 + h]);
            total += zj;
            if (j == 1) z1 = zj;
        }
        float pre = __half2float(Yb[node * 512 + h]) + (total - z1) * 0.125f + g_c[h];
        acc += tanhf(pre) * out_w[h];
    }
    #pragma unroll
    for (int o = 16; o > 0; o >>= 1) acc += __shfl_down_sync(0xffffffffu, acc, o);
    if (lane == 0) out[(node - 7) * B_SZ + b] = acc + out_b[0];
}

// ---------------- launch ---------------------------------------------------
extern "C" void kernel_launch(void* const* d_in, const int* in_sizes, int n_in,
                              void* d_out, int out_size) {
    const float* conc   = (const float*)d_in[0];   // [B, 2048]
    const float* logits = (const float*)d_in[1];   // [B, 9]
    const float* enc_w  = (const float*)d_in[2];   // [256, 1]
    const float* enc_b  = (const float*)d_in[3];   // [256]
    const float* f2n_w  = (const float*)d_in[4];   // [2304, 2048]
    const float* f2n_b  = (const float*)d_in[5];   // [2304]
    const float* msg_w  = (const float*)d_in[6];   // [256, 256]
    const float* msg_b  = (const float*)d_in[7];   // [256]
    const float* upd_w  = (const float*)d_in[8];   // [256, 512]
    const float* upd_b  = (const float*)d_in[9];   // [256]
    const float* out_w  = (const float*)d_in[10];  // [1, 256]
    const float* out_b  = (const float*)d_in[11];  // [1]
    float* out = (float*)d_out;

    __half *X, *ns, *W1, *W2, *Y;
    float *Wc;
    cudaGetSymbolAddress((void**)&X,  g_X);
    cudaGetSymbolAddress((void**)&ns, g_ns);
    cudaGetSymbolAddress((void**)&W1, g_W1);
    cudaGetSymbolAddress((void**)&W2, g_W2);
    cudaGetSymbolAddress((void**)&Y,  g_Y);
    cudaGetSymbolAddress((void**)&Wc, g_Wc);

    cudaFuncSetAttribute((const void*)gemm_mma<0>, cudaFuncAttributeMaxDynamicSharedMemorySize, SMEM_DYN);
    cudaFuncSetAttribute((const void*)gemm_mma<1>, cudaFuncAttributeMaxDynamicSharedMemorySize, SMEM_DYN);

    // fold weights; convert everything to fp16
    setup_kernel<<<513, 256>>>(upd_w, msg_w, upd_b, msg_b);
    int n4 = (B_SZ * FDIM) / 4;
    tohalf_kernel<<<(n4 + 255) / 256, 256>>>(conc, X, n4);
    n4 = (NN * HID * FDIM) / 4;
    tohalf_kernel<<<(n4 + 255) / 256, 256>>>(f2n_w, W1, n4);
    n4 = (512 * 256) / 4;
    tohalf_kernel<<<(n4 + 255) / 256, 256>>>(Wc, W2, n4);

    // ns = conc @ f2n_w^T + biases  -> fp16 node states [B*9, 256]
    gemm_mma<1><<<dim3((NN * HID) / 128, B_SZ / 128), 128, SMEM_DYN>>>(
        X, W1, FDIM, nullptr, 0,
        ns, f2n_b, enc_b, enc_w, logits);

    for (int s = 0; s < 4; ++s) {
        // Y = ns @ Wc^T : [B*9, 256] x [512, 256]^T -> [B*9, 512] fp16
        gemm_mma<0><<<dim3(512 / 128, BROWS / 128), 128, SMEM_DYN>>>(
            ns, W2, HID, Y, 512,
            nullptr, nullptr, nullptr, nullptr, nullptr);
        if (s < 3)
            combine_kernel<<<B_SZ, 256>>>(ns, Y);
        else
            final_kernel<<<B_SZ, 64>>>(Y, out_w, out_b, out);
    }
}